// round 1
// baseline (speedup 1.0000x reference)
#include <cuda_runtime.h>
#include <cstdint>

#define N_NODES 8192
#define K_IN    512
#define F_OUT   64
#define NEG_SLOPE 0.01f

// ---------------- scratch (no allocations allowed) ----------------
__device__ float g_Z[N_NODES * F_OUT];   // z = X W^T + b
__device__ float g_zi[N_NODES];
__device__ float g_zj[N_NODES];
__device__ float g_S[F_OUT];             // column sums of z

// ---------------- kernel 1: GEMM z = X (8192x512) * W^T (512x64) + b ----------------
// tile: 64 rows x 64 cols, 256 threads, 4x4 micro-tile per thread.
__global__ __launch_bounds__(256) void gemm_kernel(
    const float* __restrict__ X, const float* __restrict__ W,
    const float* __restrict__ bias)
{
    __shared__ __align__(16) float As[64][68];   // [row][k]
    __shared__ __align__(16) float Bs[64][68];   // [k][out]

    const int tid = threadIdx.x;
    const int tx = tid & 15;        // col group
    const int ty = tid >> 4;        // row group
    const int row0 = blockIdx.x * 64;

    float acc[4][4] = {};

    for (int k0 = 0; k0 < K_IN; k0 += 64) {
        // cooperative load: 1024 float4 slots, 4 per thread
        #pragma unroll
        for (int q = 0; q < 4; q++) {
            int idx = tid + 256 * q;        // 0..1023
            int r   = idx >> 4;             // 0..63
            int kk4 = (idx & 15) << 2;      // 0..60
            float4 v = *(const float4*)&X[(size_t)(row0 + r) * K_IN + k0 + kk4];
            *(float4*)&As[r][kk4] = v;
            float4 w = *(const float4*)&W[(size_t)r * K_IN + k0 + kk4]; // r = output idx
            Bs[kk4 + 0][r] = w.x;
            Bs[kk4 + 1][r] = w.y;
            Bs[kk4 + 2][r] = w.z;
            Bs[kk4 + 3][r] = w.w;
        }
        __syncthreads();

        #pragma unroll 16
        for (int kk = 0; kk < 64; kk++) {
            float a0 = As[ty * 4 + 0][kk];
            float a1 = As[ty * 4 + 1][kk];
            float a2 = As[ty * 4 + 2][kk];
            float a3 = As[ty * 4 + 3][kk];
            float4 bv = *(const float4*)&Bs[kk][tx * 4];
            acc[0][0] += a0 * bv.x; acc[0][1] += a0 * bv.y; acc[0][2] += a0 * bv.z; acc[0][3] += a0 * bv.w;
            acc[1][0] += a1 * bv.x; acc[1][1] += a1 * bv.y; acc[1][2] += a1 * bv.z; acc[1][3] += a1 * bv.w;
            acc[2][0] += a2 * bv.x; acc[2][1] += a2 * bv.y; acc[2][2] += a2 * bv.z; acc[2][3] += a2 * bv.w;
            acc[3][0] += a3 * bv.x; acc[3][1] += a3 * bv.y; acc[3][2] += a3 * bv.z; acc[3][3] += a3 * bv.w;
        }
        __syncthreads();
    }

    #pragma unroll
    for (int u = 0; u < 4; u++) {
        int r = row0 + ty * 4 + u;
        #pragma unroll
        for (int v = 0; v < 4; v++) {
            int o = tx * 4 + v;
            g_Z[(size_t)r * F_OUT + o] = acc[u][v] + bias[o];
        }
    }
}

// ---------------- kernel 2: zi = sum(a1*z), zj = sum(a2*z) per row; also zero g_S ----
// one warp per row, 8 rows per block
__global__ __launch_bounds__(256) void rowdots_kernel(
    const float* __restrict__ a1, const float* __restrict__ a2)
{
    if (blockIdx.x == 0 && threadIdx.x < F_OUT) g_S[threadIdx.x] = 0.0f;

    const int w = threadIdx.x >> 5;
    const int l = threadIdx.x & 31;
    const int i = blockIdx.x * 8 + w;

    float2 zv = *(const float2*)&g_Z[(size_t)i * F_OUT + 2 * l];
    float a1x = a1[2 * l], a1y = a1[2 * l + 1];
    float a2x = a2[2 * l], a2y = a2[2 * l + 1];
    float s1 = a1x * zv.x + a1y * zv.y;
    float s2 = a2x * zv.x + a2y * zv.y;
    #pragma unroll
    for (int off = 16; off > 0; off >>= 1) {
        s1 += __shfl_down_sync(0xFFFFFFFFu, s1, off);
        s2 += __shfl_down_sync(0xFFFFFFFFu, s2, off);
    }
    if (l == 0) { g_zi[i] = s1; g_zj[i] = s2; }
}

// ---------------- kernel 3: S = column sums of z ----------------
__global__ __launch_bounds__(256) void colsum_kernel()
{
    __shared__ float sh[4][F_OUT];
    const int o = threadIdx.x & 63;
    const int g = threadIdx.x >> 6;
    const int row0 = blockIdx.x * 64;
    float acc = 0.0f;
    for (int r = g; r < 64; r += 4)
        acc += g_Z[(size_t)(row0 + r) * F_OUT + o];
    sh[g][o] = acc;
    __syncthreads();
    if (threadIdx.x < F_OUT)
        atomicAdd(&g_S[o], sh[0][o] + sh[1][o] + sh[2][o] + sh[3][o]);
}

// ---------------- kernel 4: stream adj, per-row neighbor sum + closed-form softmax ---
// one block per row; 256 threads
__global__ __launch_bounds__(256) void attn_kernel(
    const float* __restrict__ adj, float* __restrict__ out)
{
    __shared__ int   s_idx[2048];
    __shared__ int   s_cnt;
    __shared__ int   s_diag;
    __shared__ float s_red[4][F_OUT];

    const int i = blockIdx.x;
    const int tid = threadIdx.x;

    if (tid == 0) { s_cnt = 0; s_diag = 0; }
    __syncthreads();

    // phase 1: scan row i of adj (8192 floats = 2048 float4), streaming (evict-first)
    const float4* row = (const float4*)(adj + (size_t)i * N_NODES);
    #pragma unroll
    for (int q = 0; q < 8; q++) {
        int f4 = tid + q * 256;
        float4 v = __ldcs(&row[f4]);
        int j = f4 << 2;
        if (v.x != 0.0f) { int p = atomicAdd(&s_cnt, 1); s_idx[p] = j;     if (j     == i) s_diag = 1; }
        if (v.y != 0.0f) { int p = atomicAdd(&s_cnt, 1); s_idx[p] = j + 1; if (j + 1 == i) s_diag = 1; }
        if (v.z != 0.0f) { int p = atomicAdd(&s_cnt, 1); s_idx[p] = j + 2; if (j + 2 == i) s_diag = 1; }
        if (v.w != 0.0f) { int p = atomicAdd(&s_cnt, 1); s_idx[p] = j + 3; if (j + 3 == i) s_diag = 1; }
    }
    __syncthreads();

    const int cnt = s_cnt;
    const int dg  = s_diag;

    // phase 2: R_full[o] = sum over neighbor list of z[j][o]
    const int o = tid & 63;
    const int g = tid >> 6;
    float acc = 0.0f;
    for (int p = g; p < cnt; p += 4)
        acc += __ldg(&g_Z[(size_t)s_idx[p] * F_OUT + o]);
    s_red[g][o] = acc;
    __syncthreads();

    // phase 3: closed-form softmax-weighted aggregation + residual + relu
    if (tid < F_OUT) {
        float Rfull = s_red[0][o] + s_red[1][o] + s_red[2][o] + s_red[3][o];
        float zio   = g_Z[(size_t)i * F_OUT + o];
        float Roff  = Rfull - (dg ? zio : 0.0f);
        int   koff  = cnt - dg;

        float c  = g_zi[i];
        float lc = c > 0.0f ? c : NEG_SLOPE * c;
        float e1 = expf(lc);
        float wd = 1.0f;
        if (dg) {
            float t = c + g_zj[i];
            t = t > 0.0f ? t : NEG_SLOPE * t;
            wd = expf(t);
        }
        float Zden  = (float)koff * e1 + wd + (float)(N_NODES - 1 - koff);
        float numer = (e1 - 1.0f) * Roff + (wd - 1.0f) * zio + g_S[o];
        float h = zio - numer / Zden;
        out[(size_t)i * F_OUT + o] = h > 0.0f ? h : 0.0f;
    }
}

// ---------------- launch ----------------
extern "C" void kernel_launch(void* const* d_in, const int* in_sizes, int n_in,
                              void* d_out, int out_size)
{
    const float* X    = (const float*)d_in[0];
    const float* adj  = (const float*)d_in[1];
    // d_in[2] = eye_matrix: provably identity, never read
    const float* W    = (const float*)d_in[3];
    const float* bias = (const float*)d_in[4];
    const float* a1   = (const float*)d_in[5];
    const float* a2   = (const float*)d_in[6];
    float* out        = (float*)d_out;

    gemm_kernel<<<N_NODES / 64, 256>>>(X, W, bias);
    rowdots_kernel<<<N_NODES / 8, 256>>>(a1, a2);
    colsum_kernel<<<N_NODES / 64, 256>>>();
    attn_kernel<<<N_NODES, 256>>>(adj, out);
}